// round 7
// baseline (speedup 1.0000x reference)
#include <cuda_runtime.h>
#include <cstdint>

// Upsample_72619307041391
// x: (32, 512, 512, 1) f32, kernel: (4,4) f32 -> out: (32, 1024, 1024, 1) f32
//
// out = conv1d_horiz( repeat2x2(x), kernel.flatten()[1x16], SAME(pad_left=7) )
// Collapsed: output row pairs (2r, 2r+1) identical; even output cols = 9-tap
// FIR on x (offsets -4..+4), odd cols = 8-tap FIR (offsets -3..+4).
//
// R7: 2 input rows per THREAD (6 independent LDG.128 issued up front, MLP=6),
// 4 input rows per block. 8x 4KB TMA bulk stores per block after one sync.

#define W_IN    512
#define W_OUT   1024
#define TPR     128          // threads per x-row (512/4)

__device__ __forceinline__ uint32_t smem_u32(const void* p) {
    uint32_t a;
    asm("{ .reg .u64 t; cvta.to.shared.u64 t, %1; cvt.u32.u64 %0, t; }"
        : "=r"(a) : "l"(p));
    return a;
}

__global__ __launch_bounds__(256)
void upfir_kernel(const float* __restrict__ x,
                  const float* __restrict__ ker,
                  float* __restrict__ out)
{
    __shared__ __align__(16) float srow[4][W_OUT];   // 16KB: 4 computed rows

    const int t    = threadIdx.x & (TPR - 1);     // 0..127 within row
    const int half = threadIdx.x >> 7;            // 0/1: which row-pair
    const int base = blockIdx.x * 4;              // first input row of block
    const int r0   = base + 2 * half;             // this thread's rows: r0, r0+1

    // ---- issue ALL independent global loads first (MLP = 6 + 4) ----
    const float4 zero4 = make_float4(0.f, 0.f, 0.f, 0.f);
    const float4* x0 = reinterpret_cast<const float4*>(x + (size_t)r0 * W_IN);
    const float4* x1 = reinterpret_cast<const float4*>(x + (size_t)(r0 + 1) * W_IN);

    float4 a0 = (t > 0)       ? __ldg(x0 + (t - 1)) : zero4;
    float4 b0 =                 __ldg(x0 + t);
    float4 c0 = (t < TPR - 1) ? __ldg(x0 + (t + 1)) : zero4;
    float4 a1 = (t > 0)       ? __ldg(x1 + (t - 1)) : zero4;
    float4 b1 =                 __ldg(x1 + t);
    float4 c1 = (t < TPR - 1) ? __ldg(x1 + (t + 1)) : zero4;

    const float4* k4 = reinterpret_cast<const float4*>(ker);
    const float4 ka = __ldg(k4 + 0);
    const float4 kb = __ldg(k4 + 1);
    const float4 kc = __ldg(k4 + 2);
    const float4 kd = __ldg(k4 + 3);

    // Combined phase weights.
    const float k[16] = { ka.x, ka.y, ka.z, ka.w,
                          kb.x, kb.y, kb.z, kb.w,
                          kc.x, kc.y, kc.z, kc.w,
                          kd.x, kd.y, kd.z, kd.w };
    float se[9], so[8];
    se[0] = k[0];
    #pragma unroll
    for (int d = 1; d < 8; d++) se[d] = k[2*d - 1] + k[2*d];
    se[8] = k[15];
    #pragma unroll
    for (int d = 0; d < 8; d++) so[d] = k[2*d] + k[2*d + 1];

    // ---- row r0 ----
    {
        float xs[12] = { a0.x, a0.y, a0.z, a0.w,
                         b0.x, b0.y, b0.z, b0.w,
                         c0.x, c0.y, c0.z, c0.w };
        float e0=0.f, e1=0.f, e2=0.f, e3=0.f;
        float o0=0.f, o1=0.f, o2=0.f, o3=0.f;
        #pragma unroll
        for (int d = 0; d < 9; d++) {
            const float w = se[d];
            e0 = fmaf(w, xs[d    ], e0);
            e1 = fmaf(w, xs[d + 1], e1);
            e2 = fmaf(w, xs[d + 2], e2);
            e3 = fmaf(w, xs[d + 3], e3);
        }
        #pragma unroll
        for (int d = 0; d < 8; d++) {
            const float w = so[d];
            o0 = fmaf(w, xs[d + 1], o0);
            o1 = fmaf(w, xs[d + 2], o1);
            o2 = fmaf(w, xs[d + 3], o2);
            o3 = fmaf(w, xs[d + 4], o3);
        }
        float4* s = reinterpret_cast<float4*>(&srow[2 * half][8 * t]);
        s[0] = make_float4(e0, o0, e1, o1);
        s[1] = make_float4(e2, o2, e3, o3);
    }

    // ---- row r0 + 1 ----
    {
        float xs[12] = { a1.x, a1.y, a1.z, a1.w,
                         b1.x, b1.y, b1.z, b1.w,
                         c1.x, c1.y, c1.z, c1.w };
        float e0=0.f, e1=0.f, e2=0.f, e3=0.f;
        float o0=0.f, o1=0.f, o2=0.f, o3=0.f;
        #pragma unroll
        for (int d = 0; d < 9; d++) {
            const float w = se[d];
            e0 = fmaf(w, xs[d    ], e0);
            e1 = fmaf(w, xs[d + 1], e1);
            e2 = fmaf(w, xs[d + 2], e2);
            e3 = fmaf(w, xs[d + 3], e3);
        }
        #pragma unroll
        for (int d = 0; d < 8; d++) {
            const float w = so[d];
            o0 = fmaf(w, xs[d + 1], o0);
            o1 = fmaf(w, xs[d + 2], o1);
            o2 = fmaf(w, xs[d + 3], o2);
            o3 = fmaf(w, xs[d + 4], o3);
        }
        float4* s = reinterpret_cast<float4*>(&srow[2 * half + 1][8 * t]);
        s[0] = make_float4(e0, o0, e1, o1);
        s[1] = make_float4(e2, o2, e3, o3);
    }

    __syncthreads();

    // 8 TMA bulk stores: 4 computed rows x 2 duplicates, 4KB each.
    if (threadIdx.x < 8) {
        asm volatile("fence.proxy.async.shared::cta;" ::: "memory");
        const int rowIdx = threadIdx.x >> 1;          // 0..3
        const int dup    = threadIdx.x & 1;
        const int rrow   = base + rowIdx;
        const int n = rrow >> 9;
        const int r = rrow & 511;
        float* dst = out + ((size_t)n * 1024 + 2 * (size_t)r + dup) * W_OUT;
        uint32_t src = smem_u32(&srow[rowIdx][0]);
        asm volatile(
            "cp.async.bulk.global.shared::cta.bulk_group [%0], [%1], %2;"
            :: "l"(dst), "r"(src), "r"(W_OUT * 4) : "memory");
        asm volatile("cp.async.bulk.commit_group;" ::: "memory");
        // Completion before CTA exit (SMEM lifetime + visibility).
        asm volatile("cp.async.bulk.wait_group 0;" ::: "memory");
    }
}

extern "C" void kernel_launch(void* const* d_in, const int* in_sizes, int n_in,
                              void* d_out, int out_size)
{
    const float* x   = (const float*)d_in[0];   // 32*512*512
    const float* ker = (const float*)d_in[1];   // 16 floats (4x4 row-major)
    float* out = (float*)d_out;                 // 32*1024*1024

    dim3 grid(32 * 512 / 4);   // 4096 blocks, 4 input rows each
    dim3 block(256);
    upfir_kernel<<<grid, block>>>(x, ker, out);
}

// round 9
// speedup vs baseline: 1.1381x; 1.1381x over previous
#include <cuda_runtime.h>
#include <cstdint>

// Upsample_72619307041391
// x: (32, 512, 512, 1) f32, kernel: (4,4) f32 -> out: (32, 1024, 1024, 1) f32
//
// out = conv1d_horiz( repeat2x2(x), kernel.flatten()[1x16], SAME(pad_left=7) )
// Collapsed: output row pairs (2r, 2r+1) identical; even output cols = 9-tap
// FIR on x (offsets -4..+4), odd cols = 8-tap FIR (offsets -3..+4).
//
// R9 = R4 structure + L2 residency management (cache_hint policy form, since
// bare .L2::evict_last on ld requires v8.b32 on sm_103a):
//   input x loads   -> ld.global.nc.L2::cache_hint (evict_last policy):
//                      32 MiB input stays resident in 126MB L2 across replays
//   output TMA store-> cp.async.bulk .L2::cache_hint (evict_first policy):
//                      128 MiB write stream doesn't displace the input
// Kernel is at the HBM roofline (160MiB / 24.4us = 6.9TB/s); the remaining
// lever is cutting steady-state DRAM traffic 160 -> ~128 MiB.

#define W_IN    512
#define W_OUT   1024
#define TPR     128          // threads per x-row (512/4)

__device__ __forceinline__ uint32_t smem_u32(const void* p) {
    uint32_t a;
    asm("{ .reg .u64 t; cvta.to.shared.u64 t, %1; cvt.u32.u64 %0, t; }"
        : "=r"(a) : "l"(p));
    return a;
}

__device__ __forceinline__ float4 ldg_resident(const float4* p, uint64_t pol) {
    float4 v;
    asm("ld.global.nc.L2::cache_hint.v4.f32 {%0,%1,%2,%3}, [%4], %5;"
        : "=f"(v.x), "=f"(v.y), "=f"(v.z), "=f"(v.w) : "l"(p), "l"(pol));
    return v;
}

__global__ __launch_bounds__(256)
void upfir_kernel(const float* __restrict__ x,
                  const float* __restrict__ ker,
                  float* __restrict__ out)
{
    __shared__ __align__(16) float srow[2][W_OUT];

    const int t    = threadIdx.x & (TPR - 1);     // 0..127 within row
    const int half = threadIdx.x >> 7;            // 0/1: which input row of pair
    const int row  = blockIdx.x * 2 + half;       // n*512 + r

    // L2 policies: inputs evict_last (keep resident), outputs evict_first.
    uint64_t pol_keep, pol_stream;
    asm("createpolicy.fractional.L2::evict_last.b64 %0, 1.0;"  : "=l"(pol_keep));
    asm("createpolicy.fractional.L2::evict_first.b64 %0, 1.0;" : "=l"(pol_stream));

    // FIR taps: 16 contiguous floats -> 4 vector loads (uniform broadcast).
    const float4* k4 = reinterpret_cast<const float4*>(ker);
    const float4 ka = ldg_resident(k4 + 0, pol_keep);
    const float4 kb = ldg_resident(k4 + 1, pol_keep);
    const float4 kc = ldg_resident(k4 + 2, pol_keep);
    const float4 kd = ldg_resident(k4 + 3, pol_keep);
    const float k[16] = { ka.x, ka.y, ka.z, ka.w,
                          kb.x, kb.y, kb.z, kb.w,
                          kc.x, kc.y, kc.z, kc.w,
                          kd.x, kd.y, kd.z, kd.w };

    // Combined phase weights.
    float se[9], so[8];
    se[0] = k[0];
    #pragma unroll
    for (int d = 1; d < 8; d++) se[d] = k[2*d - 1] + k[2*d];
    se[8] = k[15];
    #pragma unroll
    for (int d = 0; d < 8; d++) so[d] = k[2*d] + k[2*d + 1];

    // Load 12-value footprint: xs[j] = x[row, 4t + j - 4], zero outside [0,512)
    const float4* xr4 = reinterpret_cast<const float4*>(x + (size_t)row * W_IN);
    const float4 zero4 = make_float4(0.f, 0.f, 0.f, 0.f);
    float4 a = (t > 0)       ? ldg_resident(xr4 + (t - 1), pol_keep) : zero4;
    float4 b =                 ldg_resident(xr4 + t,       pol_keep);
    float4 c = (t < TPR - 1) ? ldg_resident(xr4 + (t + 1), pol_keep) : zero4;

    float xs[12] = { a.x, a.y, a.z, a.w,
                     b.x, b.y, b.z, b.w,
                     c.x, c.y, c.z, c.w };

    float e0=0.f, e1=0.f, e2=0.f, e3=0.f;
    float o0=0.f, o1=0.f, o2=0.f, o3=0.f;
    #pragma unroll
    for (int d = 0; d < 9; d++) {
        const float w = se[d];
        e0 = fmaf(w, xs[d    ], e0);
        e1 = fmaf(w, xs[d + 1], e1);
        e2 = fmaf(w, xs[d + 2], e2);
        e3 = fmaf(w, xs[d + 3], e3);
    }
    #pragma unroll
    for (int d = 0; d < 8; d++) {
        const float w = so[d];
        o0 = fmaf(w, xs[d + 1], o0);
        o1 = fmaf(w, xs[d + 2], o1);
        o2 = fmaf(w, xs[d + 3], o2);
        o3 = fmaf(w, xs[d + 4], o3);
    }

    float4* s = reinterpret_cast<float4*>(&srow[half][8 * t]);
    s[0] = make_float4(e0, o0, e1, o1);
    s[1] = make_float4(e2, o2, e3, o3);

    __syncthreads();
    // Order generic-proxy SMEM writes before async-proxy (TMA) reads.
    asm volatile("fence.proxy.async.shared::cta;" ::: "memory");

    // 4 TMA bulk stores per block (each computed row written twice), with an
    // evict_first L2 policy so the write stream doesn't evict the input.
    if (threadIdx.x < 4) {
        const int h   = threadIdx.x >> 1;                 // which computed row
        const int dup = threadIdx.x & 1;                  // which duplicate
        const int rrow = blockIdx.x * 2 + h;
        const int n = rrow >> 9;
        const int r = rrow & 511;
        float* dst = out + ((size_t)n * 1024 + 2 * (size_t)r + dup) * W_OUT;
        uint32_t src = smem_u32(&srow[h][0]);
        asm volatile(
            "cp.async.bulk.global.shared::cta.bulk_group.L2::cache_hint"
            " [%0], [%1], %2, %3;"
            :: "l"(dst), "r"(src), "r"(W_OUT * 4), "l"(pol_stream) : "memory");
        asm volatile("cp.async.bulk.commit_group;" ::: "memory");
        // Full completion before CTA exit (SMEM lifetime + visibility).
        asm volatile("cp.async.bulk.wait_group 0;" ::: "memory");
    }
}

extern "C" void kernel_launch(void* const* d_in, const int* in_sizes, int n_in,
                              void* d_out, int out_size)
{
    const float* x   = (const float*)d_in[0];   // 32*512*512
    const float* ker = (const float*)d_in[1];   // 16 floats (4x4 row-major)
    float* out = (float*)d_out;                 // 32*1024*1024

    dim3 grid(32 * 512 / 2);   // 8192 blocks, 2 input rows each
    dim3 block(256);
    upfir_kernel<<<grid, block>>>(x, ker, out);
}

// round 10
// speedup vs baseline: 1.1587x; 1.0180x over previous
#include <cuda_runtime.h>
#include <cstdint>

// Upsample_72619307041391
// x: (32, 512, 512, 1) f32, kernel: (4,4) f32 -> out: (32, 1024, 1024, 1) f32
//
// out = conv1d_horiz( repeat2x2(x), kernel.flatten()[1x16], SAME(pad_left=7) )
// Collapsed: output row pairs (2r, 2r+1) identical; even output cols = 9-tap
// FIR on x (offsets -4..+4), odd cols = 8-tap FIR (offsets -3..+4).
//
// R10 = R9 L2-residency hints (input evict_last / output evict_first via
// cache_hint policies) + R6 warp-autonomous stores: each warp stages its
// contiguous 1KB chunk and fires two 1KB TMA bulk stores gated only by
// __syncwarp - no block-wide convoy.

#define W_IN    512
#define W_OUT   1024
#define TPR     128          // threads per x-row (512/4)

__device__ __forceinline__ uint32_t smem_u32(const void* p) {
    uint32_t a;
    asm("{ .reg .u64 t; cvta.to.shared.u64 t, %1; cvt.u32.u64 %0, t; }"
        : "=r"(a) : "l"(p));
    return a;
}

__device__ __forceinline__ float4 ldg_resident(const float4* p, uint64_t pol) {
    float4 v;
    asm("ld.global.nc.L2::cache_hint.v4.f32 {%0,%1,%2,%3}, [%4], %5;"
        : "=f"(v.x), "=f"(v.y), "=f"(v.z), "=f"(v.w) : "l"(p), "l"(pol));
    return v;
}

__global__ __launch_bounds__(256, 8)
void upfir_kernel(const float* __restrict__ x,
                  const float* __restrict__ ker,
                  float* __restrict__ out)
{
    // One private 1KB (256-float) slice per warp.
    __shared__ __align__(16) float swarp[8][256];

    const int lane = threadIdx.x & 31;
    const int w    = threadIdx.x >> 5;            // warp 0..7
    const int t    = threadIdx.x & (TPR - 1);     // 0..127 within row
    const int half = threadIdx.x >> 7;            // 0/1: which row of the pair
    const int q    = w & 3;                       // quarter of the row
    const int row  = blockIdx.x * 2 + half;       // n*512 + r

    // L2 policies: inputs evict_last (keep resident), outputs evict_first.
    uint64_t pol_keep, pol_stream;
    asm("createpolicy.fractional.L2::evict_last.b64 %0, 1.0;"  : "=l"(pol_keep));
    asm("createpolicy.fractional.L2::evict_first.b64 %0, 1.0;" : "=l"(pol_stream));

    // FIR taps: 16 contiguous floats -> 4 vector loads (uniform broadcast).
    const float4* k4 = reinterpret_cast<const float4*>(ker);
    const float4 ka = ldg_resident(k4 + 0, pol_keep);
    const float4 kb = ldg_resident(k4 + 1, pol_keep);
    const float4 kc = ldg_resident(k4 + 2, pol_keep);
    const float4 kd = ldg_resident(k4 + 3, pol_keep);
    const float k[16] = { ka.x, ka.y, ka.z, ka.w,
                          kb.x, kb.y, kb.z, kb.w,
                          kc.x, kc.y, kc.z, kc.w,
                          kd.x, kd.y, kd.z, kd.w };

    // Combined phase weights.
    float se[9], so[8];
    se[0] = k[0];
    #pragma unroll
    for (int d = 1; d < 8; d++) se[d] = k[2*d - 1] + k[2*d];
    se[8] = k[15];
    #pragma unroll
    for (int d = 0; d < 8; d++) so[d] = k[2*d] + k[2*d + 1];

    // 12-value footprint: xs[i] = x[row, 4t + i - 4], zero outside [0,512)
    const float4* xr4 = reinterpret_cast<const float4*>(x + (size_t)row * W_IN);
    const float4 zero4 = make_float4(0.f, 0.f, 0.f, 0.f);
    float4 a = (t > 0)       ? ldg_resident(xr4 + (t - 1), pol_keep) : zero4;
    float4 b =                 ldg_resident(xr4 + t,       pol_keep);
    float4 c = (t < TPR - 1) ? ldg_resident(xr4 + (t + 1), pol_keep) : zero4;

    float xs[12] = { a.x, a.y, a.z, a.w,
                     b.x, b.y, b.z, b.w,
                     c.x, c.y, c.z, c.w };

    float e0=0.f, e1=0.f, e2=0.f, e3=0.f;
    float o0=0.f, o1=0.f, o2=0.f, o3=0.f;
    #pragma unroll
    for (int d = 0; d < 9; d++) {
        const float wgt = se[d];
        e0 = fmaf(wgt, xs[d    ], e0);
        e1 = fmaf(wgt, xs[d + 1], e1);
        e2 = fmaf(wgt, xs[d + 2], e2);
        e3 = fmaf(wgt, xs[d + 3], e3);
    }
    #pragma unroll
    for (int d = 0; d < 8; d++) {
        const float wgt = so[d];
        o0 = fmaf(wgt, xs[d + 1], o0);
        o1 = fmaf(wgt, xs[d + 2], o1);
        o2 = fmaf(wgt, xs[d + 3], o2);
        o3 = fmaf(wgt, xs[d + 4], o3);
    }

    // Stage this warp's contiguous 1KB chunk (out cols 256q .. 256q+255).
    float4* s = reinterpret_cast<float4*>(&swarp[w][8 * lane]);
    s[0] = make_float4(e0, o0, e1, o1);
    s[1] = make_float4(e2, o2, e3, o3);

    __syncwarp();

    // Lane 0 fires two 1KB bulk stores (rows 2r and 2r+1), evict_first policy.
    if (lane == 0) {
        asm volatile("fence.proxy.async.shared::cta;" ::: "memory");
        const int n = row >> 9;
        const int r = row & 511;
        float* dst = out + ((size_t)n * 1024 + 2 * (size_t)r) * W_OUT + 256 * (size_t)q;
        uint32_t src = smem_u32(&swarp[w][0]);
        asm volatile(
            "cp.async.bulk.global.shared::cta.bulk_group.L2::cache_hint"
            " [%0], [%1], %2, %3;"
            :: "l"(dst), "r"(src), "r"(256 * 4), "l"(pol_stream) : "memory");
        asm volatile(
            "cp.async.bulk.global.shared::cta.bulk_group.L2::cache_hint"
            " [%0], [%1], %2, %3;"
            :: "l"(dst + W_OUT), "r"(src), "r"(256 * 4), "l"(pol_stream) : "memory");
        asm volatile("cp.async.bulk.commit_group;" ::: "memory");
        // Completion before CTA exit (SMEM lifetime + visibility).
        asm volatile("cp.async.bulk.wait_group 0;" ::: "memory");
    }
}

extern "C" void kernel_launch(void* const* d_in, const int* in_sizes, int n_in,
                              void* d_out, int out_size)
{
    const float* x   = (const float*)d_in[0];   // 32*512*512
    const float* ker = (const float*)d_in[1];   // 16 floats (4x4 row-major)
    float* out = (float*)d_out;                 // 32*1024*1024

    dim3 grid(32 * 512 / 2);   // 8192 blocks, 2 input rows each
    dim3 block(256);
    upfir_kernel<<<grid, block>>>(x, ker, out);
}